// round 16
// baseline (speedup 1.0000x reference)
#include <cuda_runtime.h>
#include <cuda_fp16.h>

#define NN 1024
#define EPSF 1e-5f
#define INFF 1e5f

typedef unsigned long long u64;
typedef unsigned int u32;

// ---------------- device scratch --------------------------------------------------
__device__ float g_A[NN * 64];                  // h@ew1[0:64] + eb1
__device__ float g_Bt[64 * NN];                 // h@ew1[64:128], k-major [k][j]
__device__ float g_w[NN * NN];
__device__ float g_wsum[NN];
__device__ __align__(16) float g_cv[NN * 64];
__device__ __align__(16) float g_M[NN * 192];   // M[i][k][d] = sum_j S * dir
__device__ __align__(16) float g_Dsum[NN * 4];  // padded to /4
__device__ __align__(16) float g_xacc[NN * 4];  // padded to /4
// folded weights
__device__ __half g_Wh[64 * 128];               // fp16, row k: [ew2@cw1 | ew2@fw1]
__device__ float g_bc[64];                      // eb2@cw1 + cb1
__device__ float g_bf1a[64];                    // eb2@fw1
__device__ float g_waw[64];                     // ew2@aw
__device__ float g_baw[1];                      // eb2.aw + ab
__device__ float g_Cw[64];                      // ew1 row 128

// ---------------- helpers ---------------------------------------------------------
__device__ __forceinline__ __half2 u2h2(u32 u) {
    __half2 h;
    *reinterpret_cast<u32*>(&h) = u;
    return h;
}
__device__ __forceinline__ float silu_f(float v) {          // exact-ish (2 MUFU)
    return __fdividef(v, 1.f + __expf(-v));
}
__device__ __forceinline__ float silu_fast(float v) {       // 1 MUFU via tanh
    float t;
    asm("tanh.approx.f32 %0, %1;" : "=f"(t) : "f"(0.5f * v));
    return v * fmaf(0.5f, t, 0.5f);
}
__device__ __forceinline__ __half2 silu_h2(__half2 z) {     // 2 silus, 1 MUFU
    const __half2 h05 = __float2half2_rn(0.5f);
    __half2 zh = __hmul2(z, h05);
    u32 zi = *reinterpret_cast<u32*>(&zh), ti;
    asm("tanh.approx.f16x2 %0, %1;" : "=r"(ti) : "r"(zi));
    __half2 t = *reinterpret_cast<__half2*>(&ti);
    return __hmul2(z, __hfma2(t, h05, h05));
}

// ---------------- k_prep: fold + node_pre + zero, block-range dispatch -------------
// grid layout (64-thread blocks):
//   [0,64)        : fold row b
//   64            : fold extras (waw, bc, bf1a, Cw, baw)
//   [65,1089)     : node_pre for i = b-65
//   [1089,1857)   : zero g_M     (768 blocks x 64 f4)
//   [1857,2113)   : zero g_cv    (256 blocks x 64 f4)
//   [2113,2129)   : zero g_xacc  (16 blocks x 64 f4 = 1024 f4 = NN*4 floats)
//   [2129,2145)   : zero g_Dsum  (16 blocks x 64 f4)
#define PREP_GRID 2145
__global__ void k_prep(const float* __restrict__ h, const float* __restrict__ ew1,
                       const float* __restrict__ eb1, const float* __restrict__ ew2,
                       const float* __restrict__ eb2, const float* __restrict__ cw1,
                       const float* __restrict__ cb1, const float* __restrict__ fw1,
                       const float* __restrict__ aw, const float* __restrict__ ab) {
    int b = blockIdx.x, tid = threadIdx.x;
    if (b < 64) {
        __shared__ float se[64];
        se[tid] = ew2[b * 64 + tid];
        __syncthreads();
        float ac = 0.f, af = 0.f;
#pragma unroll 8
        for (int k = 0; k < 64; k++) {
            float e = se[k];
            ac += e * cw1[k * 64 + tid];
            af += e * fw1[k * 64 + tid];
        }
        g_Wh[b * 128 + tid] = __float2half(ac);
        g_Wh[b * 128 + 64 + tid] = __float2half(af);
    } else if (b == 64) {
        float sw = 0.f;
        for (int k = 0; k < 64; k++) sw += ew2[tid * 64 + k] * aw[k];
        g_waw[tid] = sw;
        float bc = cb1[tid], bf = 0.f;
        for (int k = 0; k < 64; k++) {
            bc += eb2[k] * cw1[k * 64 + tid];
            bf += eb2[k] * fw1[k * 64 + tid];
        }
        g_bc[tid] = bc;
        g_bf1a[tid] = bf;
        g_Cw[tid] = ew1[128 * 64 + tid];
        if (tid == 0) {
            float s = ab[0];
            for (int k = 0; k < 64; k++) s += eb2[k] * aw[k];
            g_baw[0] = s;
        }
    } else if (b < 1089) {
        int i = b - 65;
        __shared__ float hr[64];
        hr[tid] = h[i * 64 + tid];
        __syncthreads();
        float a = eb1[tid], bb = 0.f;
#pragma unroll 8
        for (int m = 0; m < 64; m++) {
            float hm = hr[m];
            a += hm * ew1[m * 64 + tid];
            bb += hm * ew1[(64 + m) * 64 + tid];
        }
        g_A[i * 64 + tid] = a;
        g_Bt[tid * NN + i] = bb;
    } else {
        const float4 z4 = make_float4(0.f, 0.f, 0.f, 0.f);
        if (b < 1857) {
            reinterpret_cast<float4*>(g_M)[(b - 1089) * 64 + tid] = z4;
        } else if (b < 2113) {
            reinterpret_cast<float4*>(g_cv)[(b - 1857) * 64 + tid] = z4;
        } else if (b < 2129) {
            reinterpret_cast<float4*>(g_xacc)[(b - 2113) * 64 + tid] = z4;
        } else {
            reinterpret_cast<float4*>(g_Dsum)[(b - 2129) * 64 + tid] = z4;
        }
    }
}

// ---------------- k_edge_attn: fused slog + softmax combine -----------------------
__global__ void __launch_bounds__(256) k_edge_attn(const float* __restrict__ x,
                                                   const float* __restrict__ lg) {
    __shared__ float sls[NN], sle[NN];
    __shared__ float sA[64], sC[64], sW[64];
    __shared__ float red[24];
    int i = blockIdx.x, tid = threadIdx.x;
    int lane = tid & 31, wid = tid >> 5;
    if (tid < 64) {
        sA[tid] = g_A[i * 64 + tid];
        sC[tid] = g_Cw[tid];
        sW[tid] = g_waw[tid];
    }
    __syncthreads();
    float gamma = __expf(lg[0]);
    float baw = g_baw[0];
    float xi0 = x[i * 3 + 0], xi1 = x[i * 3 + 1], xi2 = x[i * 3 + 2];

    for (int j = tid; j < NN; j += 256) {
        float dx = xi0 - x[j * 3 + 0];
        float dy = xi1 - x[j * 3 + 1];
        float dz = xi2 - x[j * 3 + 2];
        float nrm = sqrtf(dx * dx + dy * dy + dz * dz + EPSF);
        float slog = baw;
#pragma unroll 8
        for (int k = 0; k < 64; k++)
            slog += silu_fast(sA[k] + g_Bt[k * NN + j] + nrm * sC[k]) * sW[k];
        slog = (slog > 0.f) ? slog : 0.01f * slog;
        float diag = (j == i) ? INFF : 0.f;
        sle[j] = -(nrm + diag) * gamma;
        sls[j] = slog - diag;
    }
    __syncthreads();

    float m = -3.4e38f;
    for (int j = tid; j < NN; j += 256) m = fmaxf(m, sls[j]);
#pragma unroll
    for (int o = 16; o; o >>= 1) m = fmaxf(m, __shfl_xor_sync(~0u, m, o));
    if (lane == 0) red[wid] = m;
    __syncthreads();
    m = red[0];
#pragma unroll
    for (int t = 1; t < 8; t++) m = fmaxf(m, red[t]);

    float ze = 0.f, zs = 0.f, tt = 0.f;
    for (int j = tid; j < NN; j += 256) {
        float le = sle[j], ls = sls[j] - m;
        ze += __expf(le);
        zs += __expf(ls);
        tt += __expf(le + ls);
    }
#pragma unroll
    for (int o = 16; o; o >>= 1) {
        ze += __shfl_xor_sync(~0u, ze, o);
        zs += __shfl_xor_sync(~0u, zs, o);
        tt += __shfl_xor_sync(~0u, tt, o);
    }
    __syncthreads();
    if (lane == 0) { red[wid] = ze; red[8 + wid] = zs; red[16 + wid] = tt; }
    __syncthreads();
    ze = zs = tt = 0.f;
#pragma unroll
    for (int t = 0; t < 8; t++) { ze += red[t]; zs += red[8 + t]; tt += red[16 + t]; }

    float inv = 1.f / (tt + EPSF * ze * zs);
    for (int j = tid; j < NN; j += 256)
        g_w[i * NN + j] = __expf(sle[j] + sls[j] - m) * inv;
    if (tid == 0) g_wsum[i] = tt * inv;
}

// ---------------- K4: fused pair kernel (bias-folded acc init) --------------------
// smem float offsets
#define OFF_WH   0          // 4096 floats = 8192 halfs (folded weights)
#define OFF_SVH  4096       // half[64 x 258]: v then S in-place (column-private)
#define SVH_STR  258
#define OFF_SWT  12352      // 256 (w)
#define OFF_BC2  12608      // half2[32] = 32 floats
#define OFF_BF2  12640      // half2[32] = 32 floats
#define OFF_FB1H 12672      // half2[32] = 32 floats
#define OFF_CW2H 12704      // half2[32] = 32 floats
#define OFF_A    12736      // 64
#define OFF_C    12800      // 64
#define OFF_XI   12864      // 4
#define OFF_CVP  12868      // 256
#define OFF_DIR  13124      // 3 x 256 fp32 (xacc/Dsum threads)
#define OFF_SDH  13892      // half[3 x 260] dirs = 390 floats (M epilogue)
#define OFF_SPHI 14284      // 256
#define K4_FLOATS 14540     // 58160 B

__global__ void __launch_bounds__(256, 3) k_pair(const float* __restrict__ x,
                                                 const float* __restrict__ fb1,
                                                 const float* __restrict__ cw2) {
    extern __shared__ __align__(16) float dyn[];
    __half* sWh = reinterpret_cast<__half*>(dyn + OFF_WH);
    __half* svh = reinterpret_cast<__half*>(dyn + OFF_SVH);
    __half* sdh = reinterpret_cast<__half*>(dyn + OFF_SDH);
    float* swt = dyn + OFF_SWT;

    int i = blockIdx.y, tid = threadIdx.x;
    int j = blockIdx.x * 256 + tid;

    {
        const uint4* gW = reinterpret_cast<const uint4*>(g_Wh);
        uint4* sW = reinterpret_cast<uint4*>(sWh);
        for (int t = tid; t < 1024; t += 256) sW[t] = gW[t];
    }
    if (tid < 32) {
        reinterpret_cast<__half2*>(dyn + OFF_BC2)[tid] =
            __floats2half2_rn(g_bc[2 * tid], g_bc[2 * tid + 1]);
        reinterpret_cast<__half2*>(dyn + OFF_BF2)[tid] =
            __floats2half2_rn(g_bf1a[2 * tid], g_bf1a[2 * tid + 1]);
        reinterpret_cast<__half2*>(dyn + OFF_FB1H)[tid] =
            __floats2half2_rn(fb1[2 * tid], fb1[2 * tid + 1]);
        reinterpret_cast<__half2*>(dyn + OFF_CW2H)[tid] =
            __floats2half2_rn(cw2[2 * tid], cw2[2 * tid + 1]);
    }
    if (tid < 64) {
        dyn[OFF_A + tid] = g_A[i * 64 + tid];
        dyn[OFF_C + tid] = g_Cw[tid];
    }
    if (tid < 3) dyn[OFF_XI + tid] = x[i * 3 + tid];
    __syncthreads();

    // ---- phase A: geometry + v (fast silu fp32; store fp16, column-private) ----
    float dxr0 = dyn[OFF_XI + 0] - x[j * 3 + 0];
    float dxr1 = dyn[OFF_XI + 1] - x[j * 3 + 1];
    float dxr2 = dyn[OFF_XI + 2] - x[j * 3 + 2];
    float nrm = sqrtf(dxr0 * dxr0 + dxr1 * dxr1 + dxr2 * dxr2 + EPSF);
    float inv1 = __fdividef(1.f, nrm + 1.f);
    float w = g_w[i * NN + j];
    swt[tid] = w;
    float d0 = dxr0 * inv1, d1 = dxr1 * inv1, d2 = dxr2 * inv1;
    dyn[OFF_DIR + 0 * 256 + tid] = d0;
    dyn[OFF_DIR + 1 * 256 + tid] = d1;
    dyn[OFF_DIR + 2 * 256 + tid] = d2;
    sdh[0 * 260 + tid] = __float2half(d0);
    sdh[1 * 260 + tid] = __float2half(d1);
    sdh[2 * 260 + tid] = __float2half(d2);

#pragma unroll 8
    for (int k = 0; k < 64; k++) {
        float b = g_Bt[k * NN + j];
        svh[k * SVH_STR + tid] = __float2half(silu_fast(dyn[OFF_A + k] + b + nrm * dyn[OFF_C + k]));
    }
    __syncthreads();

    // ---- cv = sum_j w*v (fp32, sensitive path) ----
    {
        int k = tid & 63, qq = tid >> 6;
        const __half2* vp = reinterpret_cast<const __half2*>(svh + k * SVH_STR + qq * 64);
        const float* wp = swt + qq * 64;
        float sacc = 0.f;
#pragma unroll 8
        for (int m = 0; m < 32; m++) {
            __half2 p = vp[m];
            sacc += wp[2 * m] * __low2float(p) + wp[2 * m + 1] * __high2float(p);
        }
        dyn[OFF_CVP + k * 4 + qq] = sacc;
    }
    __syncthreads();
    if (tid < 64) {
        const float4 p = *reinterpret_cast<const float4*>(dyn + OFF_CVP + tid * 4);
        atomicAdd(&g_cv[i * 64 + tid], p.x + p.y + p.z + p.w);
    }

    const __half2 hz = __float2half2_rn(0.f);

    // ---- pass 1: Pc = v @ Wc + bc (acc init = bc2) -> phi ----
    {
        const __half2* bc2 = reinterpret_cast<const __half2*>(dyn + OFF_BC2);
        __half2 acc[32];
#pragma unroll
        for (int t = 0; t < 32; t++) acc[t] = bc2[t];
#pragma unroll 4
        for (int kk = 0; kk < 64; kk++) {
            __half2 v2 = __half2half2(svh[kk * SVH_STR + tid]);
            const uint4* wr = reinterpret_cast<const uint4*>(sWh + kk * 128);
#pragma unroll
            for (int c = 0; c < 8; c++) {
                uint4 q = wr[c];
                acc[4 * c + 0] = __hfma2(v2, u2h2(q.x), acc[4 * c + 0]);
                acc[4 * c + 1] = __hfma2(v2, u2h2(q.y), acc[4 * c + 1]);
                acc[4 * c + 2] = __hfma2(v2, u2h2(q.z), acc[4 * c + 2]);
                acc[4 * c + 3] = __hfma2(v2, u2h2(q.w), acc[4 * c + 3]);
            }
        }
        const __half2* cw2h = reinterpret_cast<const __half2*>(dyn + OFF_CW2H);
        __half2 ph2 = hz;
#pragma unroll
        for (int t = 0; t < 32; t++)
            ph2 = __hfma2(silu_h2(acc[t]), cw2h[t], ph2);
        float phi = __low2float(ph2) + __high2float(ph2);
        dyn[OFF_SPHI + tid] = phi * (nrm + 1.f);  // xacc = sum dir * sphi
    }

    // ---- pass 2: Pf = v @ Wf + bf (acc init = bf2) -> S in-place ----
    {
        const __half2* bf2 = reinterpret_cast<const __half2*>(dyn + OFF_BF2);
        __half2 acc[32];
#pragma unroll
        for (int t = 0; t < 32; t++) acc[t] = bf2[t];
#pragma unroll 4
        for (int kk = 0; kk < 64; kk++) {
            __half2 v2 = __half2half2(svh[kk * SVH_STR + tid]);
            const uint4* wr = reinterpret_cast<const uint4*>(sWh + kk * 128 + 64);
#pragma unroll
            for (int c = 0; c < 8; c++) {
                uint4 q = wr[c];
                acc[4 * c + 0] = __hfma2(v2, u2h2(q.x), acc[4 * c + 0]);
                acc[4 * c + 1] = __hfma2(v2, u2h2(q.y), acc[4 * c + 1]);
                acc[4 * c + 2] = __hfma2(v2, u2h2(q.z), acc[4 * c + 2]);
                acc[4 * c + 3] = __hfma2(v2, u2h2(q.w), acc[4 * c + 3]);
            }
        }
        const __half2* fb1h = reinterpret_cast<const __half2*>(dyn + OFF_FB1H);
        __half2 w2 = __float2half2_rn(w);
#pragma unroll
        for (int t = 0; t < 32; t++) {
            __half2 s2 = silu_h2(__hfma2(w2, acc[t], fb1h[t]));
            svh[(2 * t) * SVH_STR + tid] = __low2half(s2);
            svh[(2 * t + 1) * SVH_STR + tid] = __high2half(s2);
        }
    }
    __syncthreads();

    // ---- epilogue: M[k][d] (half2 chunked), xacc, Dsum ----
    if (tid < 192) {
        int k = tid / 3, d = tid - 3 * k;
        const __half2* sp = reinterpret_cast<const __half2*>(svh + k * SVH_STR);
        const __half2* dph = reinterpret_cast<const __half2*>(sdh + d * 260);
        float accf = 0.f;
#pragma unroll
        for (int ch = 0; ch < 4; ch++) {
            __half2 a2 = hz;
#pragma unroll 8
            for (int m = ch * 32; m < ch * 32 + 32; m++) a2 = __hfma2(sp[m], dph[m], a2);
            accf += __low2float(a2) + __high2float(a2);
        }
        atomicAdd(&g_M[i * 192 + k * 3 + d], accf);
    } else if (tid < 195) {
        int d = tid - 192;
        const float* dp = dyn + OFF_DIR + d * 256;
        const float* pp = dyn + OFF_SPHI;
        float sacc = 0.f;
#pragma unroll 8
        for (int jj = 0; jj < 256; jj++) sacc += dp[jj] * pp[jj];
        atomicAdd(&g_xacc[i * 4 + d], sacc);
    } else if (tid < 198) {
        int d = tid - 195;
        const float* dp = dyn + OFF_DIR + d * 256;
        float sacc = 0.f;
#pragma unroll 8
        for (int jj = 0; jj < 256; jj++) sacc += dp[jj];
        atomicAdd(&g_Dsum[i * 4 + d], sacc);
    }
}

// ---------------- K6: node-level MLPs + outputs (4 nodes / 256-thread block) ------
__global__ void __launch_bounds__(256) k_final(
        const float* __restrict__ h, const float* __restrict__ x,
        const float* __restrict__ ew2, const float* __restrict__ eb2,
        const float* __restrict__ nw1, const float* __restrict__ nb1,
        const float* __restrict__ nw2, const float* __restrict__ nb2,
        const float* __restrict__ pw1, const float* __restrict__ pb1,
        const float* __restrict__ pw2, const float* __restrict__ pb2,
        const float* __restrict__ fw2, const float* __restrict__ fb2,
        float* __restrict__ out, int write_x) {
    __shared__ float sM[4][192], sq[4][32], p1[4][64], nin[4][192], n1[4][64], scv[4][64];
    int li = threadIdx.x >> 6, t = threadIdx.x & 63;
    int i = blockIdx.x * 4 + li;
    scv[li][t] = g_cv[i * 64 + t];
    for (int tt = t; tt < 192; tt += 64) sM[li][tt] = g_M[i * 192 + tt];
    __syncthreads();
    if (t < 32) {
        int c = t;
        float ds0 = g_Dsum[i * 4 + 0], ds1 = g_Dsum[i * 4 + 1], ds2 = g_Dsum[i * 4 + 2];
        float fb = fb2[c];
        float a0 = fb * ds0, a1 = fb * ds1, a2 = fb * ds2;
#pragma unroll 8
        for (int k = 0; k < 64; k++) {
            float f = fw2[k * 32 + c];
            a0 += f * sM[li][k * 3 + 0];
            a1 += f * sM[li][k * 3 + 1];
            a2 += f * sM[li][k * 3 + 2];
        }
        a0 *= (1.f / 1024.f);
        a1 *= (1.f / 1024.f);
        a2 *= (1.f / 1024.f);
        sq[li][c] = a0 * a0 + a1 * a1 + a2 * a2;
    }
    __syncthreads();
    {
        float a = g_wsum[i] * eb2[t];
#pragma unroll 8
        for (int m = 0; m < 64; m++) a += scv[li][m] * ew2[m * 64 + t];
        nin[li][64 + t] = a;
        float b = pb1[t];
#pragma unroll
        for (int c = 0; c < 32; c++) b += sq[li][c] * pw1[c * 64 + t];
        p1[li][t] = silu_f(b);
        nin[li][t] = h[i * 64 + t];
    }
    __syncthreads();
    {
        float a = pb2[t];
#pragma unroll 8
        for (int m = 0; m < 64; m++) a += p1[li][m] * pw2[m * 64 + t];
        nin[li][128 + t] = a;
    }
    __syncthreads();
    {
        float a = nb1[t];
#pragma unroll 8
        for (int m = 0; m < 192; m++) a += nin[li][m] * nw1[m * 64 + t];
        n1[li][t] = silu_f(a);
    }
    __syncthreads();
    {
        float a = nb2[t];
#pragma unroll 8
        for (int m = 0; m < 64; m++) a += n1[li][m] * nw2[m * 64 + t];
        out[i * 64 + t] = h[i * 64 + t] + a;
    }
    if (write_x && t < 3)
        out[NN * 64 + i * 3 + t] = x[i * 3 + t] + g_xacc[i * 4 + t] * (1.f / 1024.f);
}

// ---------------- host -------------------------------------------------------------
extern "C" void kernel_launch(void* const* d_in, const int* in_sizes, int n_in,
                              void* d_out, int out_size) {
    const float* h = (const float*)d_in[0];
    const float* x = (const float*)d_in[1];
    const float* ew1 = (const float*)d_in[2];
    const float* eb1 = (const float*)d_in[3];
    const float* ew2 = (const float*)d_in[4];
    const float* eb2 = (const float*)d_in[5];
    const float* nw1 = (const float*)d_in[6];
    const float* nb1 = (const float*)d_in[7];
    const float* nw2 = (const float*)d_in[8];
    const float* nb2 = (const float*)d_in[9];
    const float* cw1 = (const float*)d_in[10];
    const float* cb1 = (const float*)d_in[11];
    const float* cw2 = (const float*)d_in[12];
    const float* aw = (const float*)d_in[13];
    const float* ab = (const float*)d_in[14];
    const float* fw1 = (const float*)d_in[15];
    const float* fb1 = (const float*)d_in[16];
    const float* fw2 = (const float*)d_in[17];
    const float* fb2 = (const float*)d_in[18];
    const float* pw1 = (const float*)d_in[19];
    const float* pb1 = (const float*)d_in[20];
    const float* pw2 = (const float*)d_in[21];
    const float* pb2 = (const float*)d_in[22];
    const float* lg = (const float*)d_in[23];
    float* out = (float*)d_out;

    const int K4_SMEM = K4_FLOATS * sizeof(float);  // 58160 B
    cudaFuncSetAttribute(k_pair, cudaFuncAttributeMaxDynamicSharedMemorySize, K4_SMEM);

    int write_x = (out_size >= NN * 64 + NN * 3) ? 1 : 0;

    k_prep<<<PREP_GRID, 64>>>(h, ew1, eb1, ew2, eb2, cw1, cb1, fw1, aw, ab);
    k_edge_attn<<<NN, 256>>>(x, lg);
    k_pair<<<dim3(NN / 256, NN), 256, K4_SMEM>>>(x, fb1, cw2);
    k_final<<<NN / 4, 256>>>(h, x, ew2, eb2, nw1, nb1, nw2, nb2, pw1, pb1, pw2, pb2,
                             fw2, fb2, out, write_x);
}

// round 17
// speedup vs baseline: 1.0156x; 1.0156x over previous
#include <cuda_runtime.h>
#include <cuda_fp16.h>

#define NN 1024
#define EPSF 1e-5f
#define INFF 1e5f

typedef unsigned long long u64;
typedef unsigned int u32;

// ---------------- device scratch --------------------------------------------------
__device__ float g_A[NN * 64];                  // h@ew1[0:64] + eb1
__device__ float g_Bt[64 * NN];                 // h@ew1[64:128], k-major [k][j]
__device__ float g_w[NN * NN];
__device__ float g_wsum[NN];
__device__ __align__(16) float g_cv[NN * 64];
__device__ __align__(16) float g_M[NN * 192];   // M[i][k][d] = sum_j S * dir
__device__ __align__(16) float g_Dsum[NN * 4];  // padded to /4
__device__ __align__(16) float g_xacc[NN * 4];  // padded to /4
// folded weights
__device__ __half g_Wh[64 * 128];               // fp16, row k: [ew2@cw1 | ew2@fw1]
__device__ float g_bc[64];                      // eb2@cw1 + cb1
__device__ float g_bf1a[64];                    // eb2@fw1
__device__ float g_waw[64];                     // ew2@aw
__device__ float g_baw[1];                      // eb2.aw + ab
__device__ float g_Cw[64];                      // ew1 row 128

// ---------------- helpers ---------------------------------------------------------
__device__ __forceinline__ __half2 u2h2(u32 u) {
    __half2 h;
    *reinterpret_cast<u32*>(&h) = u;
    return h;
}
__device__ __forceinline__ float silu_f(float v) {          // exact-ish (2 MUFU)
    return __fdividef(v, 1.f + __expf(-v));
}
__device__ __forceinline__ float silu_fast(float v) {       // 1 MUFU via tanh
    float t;
    asm("tanh.approx.f32 %0, %1;" : "=f"(t) : "f"(0.5f * v));
    return v * fmaf(0.5f, t, 0.5f);
}
__device__ __forceinline__ __half2 silu_h2(__half2 z) {     // 2 silus, 1 MUFU
    const __half2 h05 = __float2half2_rn(0.5f);
    __half2 zh = __hmul2(z, h05);
    u32 zi = *reinterpret_cast<u32*>(&zh), ti;
    asm("tanh.approx.f16x2 %0, %1;" : "=r"(ti) : "r"(zi));
    __half2 t = *reinterpret_cast<__half2*>(&ti);
    return __hmul2(z, __hfma2(t, h05, h05));
}

// ---------------- k_prep: fold + node_pre + zero, block-range dispatch -------------
#define PREP_GRID 2145
__global__ void k_prep(const float* __restrict__ h, const float* __restrict__ ew1,
                       const float* __restrict__ eb1, const float* __restrict__ ew2,
                       const float* __restrict__ eb2, const float* __restrict__ cw1,
                       const float* __restrict__ cb1, const float* __restrict__ fw1,
                       const float* __restrict__ aw, const float* __restrict__ ab) {
    int b = blockIdx.x, tid = threadIdx.x;
    if (b < 64) {
        __shared__ float se[64];
        se[tid] = ew2[b * 64 + tid];
        __syncthreads();
        float ac = 0.f, af = 0.f;
#pragma unroll 8
        for (int k = 0; k < 64; k++) {
            float e = se[k];
            ac += e * cw1[k * 64 + tid];
            af += e * fw1[k * 64 + tid];
        }
        g_Wh[b * 128 + tid] = __float2half(ac);
        g_Wh[b * 128 + 64 + tid] = __float2half(af);
    } else if (b == 64) {
        float sw = 0.f;
        for (int k = 0; k < 64; k++) sw += ew2[tid * 64 + k] * aw[k];
        g_waw[tid] = sw;
        float bc = cb1[tid], bf = 0.f;
        for (int k = 0; k < 64; k++) {
            bc += eb2[k] * cw1[k * 64 + tid];
            bf += eb2[k] * fw1[k * 64 + tid];
        }
        g_bc[tid] = bc;
        g_bf1a[tid] = bf;
        g_Cw[tid] = ew1[128 * 64 + tid];
        if (tid == 0) {
            float s = ab[0];
            for (int k = 0; k < 64; k++) s += eb2[k] * aw[k];
            g_baw[0] = s;
        }
    } else if (b < 1089) {
        int i = b - 65;
        __shared__ float hr[64];
        hr[tid] = h[i * 64 + tid];
        __syncthreads();
        float a = eb1[tid], bb = 0.f;
#pragma unroll 8
        for (int m = 0; m < 64; m++) {
            float hm = hr[m];
            a += hm * ew1[m * 64 + tid];
            bb += hm * ew1[(64 + m) * 64 + tid];
        }
        g_A[i * 64 + tid] = a;
        g_Bt[tid * NN + i] = bb;
    } else {
        const float4 z4 = make_float4(0.f, 0.f, 0.f, 0.f);
        if (b < 1857) {
            reinterpret_cast<float4*>(g_M)[(b - 1089) * 64 + tid] = z4;
        } else if (b < 2113) {
            reinterpret_cast<float4*>(g_cv)[(b - 1857) * 64 + tid] = z4;
        } else if (b < 2129) {
            reinterpret_cast<float4*>(g_xacc)[(b - 2113) * 64 + tid] = z4;
        } else {
            reinterpret_cast<float4*>(g_Dsum)[(b - 2129) * 64 + tid] = z4;
        }
    }
}

// ---------------- k_edge_attn: fused slog + softmax combine -----------------------
__global__ void __launch_bounds__(256) k_edge_attn(const float* __restrict__ x,
                                                   const float* __restrict__ lg) {
    __shared__ float sls[NN], sle[NN];
    __shared__ float sA[64], sC[64], sW[64];
    __shared__ float red[24];
    int i = blockIdx.x, tid = threadIdx.x;
    int lane = tid & 31, wid = tid >> 5;
    if (tid < 64) {
        sA[tid] = g_A[i * 64 + tid];
        sC[tid] = g_Cw[tid];
        sW[tid] = g_waw[tid];
    }
    __syncthreads();
    float gamma = __expf(lg[0]);
    float baw = g_baw[0];
    float xi0 = x[i * 3 + 0], xi1 = x[i * 3 + 1], xi2 = x[i * 3 + 2];

    for (int j = tid; j < NN; j += 256) {
        float dx = xi0 - x[j * 3 + 0];
        float dy = xi1 - x[j * 3 + 1];
        float dz = xi2 - x[j * 3 + 2];
        float nrm = sqrtf(dx * dx + dy * dy + dz * dz + EPSF);
        float slog = baw;
#pragma unroll 8
        for (int k = 0; k < 64; k++)
            slog += silu_fast(sA[k] + g_Bt[k * NN + j] + nrm * sC[k]) * sW[k];
        slog = (slog > 0.f) ? slog : 0.01f * slog;
        float diag = (j == i) ? INFF : 0.f;
        sle[j] = -(nrm + diag) * gamma;
        sls[j] = slog - diag;
    }
    __syncthreads();

    float m = -3.4e38f;
    for (int j = tid; j < NN; j += 256) m = fmaxf(m, sls[j]);
#pragma unroll
    for (int o = 16; o; o >>= 1) m = fmaxf(m, __shfl_xor_sync(~0u, m, o));
    if (lane == 0) red[wid] = m;
    __syncthreads();
    m = red[0];
#pragma unroll
    for (int t = 1; t < 8; t++) m = fmaxf(m, red[t]);

    float ze = 0.f, zs = 0.f, tt = 0.f;
    for (int j = tid; j < NN; j += 256) {
        float le = sle[j], ls = sls[j] - m;
        ze += __expf(le);
        zs += __expf(ls);
        tt += __expf(le + ls);
    }
#pragma unroll
    for (int o = 16; o; o >>= 1) {
        ze += __shfl_xor_sync(~0u, ze, o);
        zs += __shfl_xor_sync(~0u, zs, o);
        tt += __shfl_xor_sync(~0u, tt, o);
    }
    __syncthreads();
    if (lane == 0) { red[wid] = ze; red[8 + wid] = zs; red[16 + wid] = tt; }
    __syncthreads();
    ze = zs = tt = 0.f;
#pragma unroll
    for (int t = 0; t < 8; t++) { ze += red[t]; zs += red[8 + t]; tt += red[16 + t]; }

    float inv = 1.f / (tt + EPSF * ze * zs);
    for (int j = tid; j < NN; j += 256)
        g_w[i * NN + j] = __expf(sle[j] + sls[j] - m) * inv;
    if (tid == 0) g_wsum[i] = tt * inv;
}

// ---------------- K4: fused pair kernel (bias-folded acc init) --------------------
// smem float offsets
#define OFF_WH   0          // 4096 floats = 8192 halfs (folded weights)
#define OFF_SVH  4096       // half[64 x 258]: v then S in-place (column-private)
#define SVH_STR  258
#define OFF_SWT  12352      // 256 (w)
#define OFF_BC2  12608      // half2[32] = 32 floats
#define OFF_BF2  12640      // half2[32] = 32 floats
#define OFF_FB1H 12672      // half2[32] = 32 floats
#define OFF_CW2H 12704      // half2[32] = 32 floats
#define OFF_A    12736      // 64
#define OFF_C    12800      // 64
#define OFF_XI   12864      // 4
#define OFF_CVP  12868      // 256
#define OFF_DIR  13124      // 3 x 256 fp32 (xacc/Dsum threads)
#define OFF_SDH  13892      // half[3 x 260] dirs = 390 floats (M epilogue)
#define OFF_SPHI 14284      // 256
#define K4_FLOATS 14540     // 58160 B

__global__ void __launch_bounds__(256, 3) k_pair(const float* __restrict__ x,
                                                 const float* __restrict__ fb1,
                                                 const float* __restrict__ cw2) {
    extern __shared__ __align__(16) float dyn[];
    __half* sWh = reinterpret_cast<__half*>(dyn + OFF_WH);
    __half* svh = reinterpret_cast<__half*>(dyn + OFF_SVH);
    __half* sdh = reinterpret_cast<__half*>(dyn + OFF_SDH);
    float* swt = dyn + OFF_SWT;

    int i = blockIdx.y, tid = threadIdx.x;
    int j = blockIdx.x * 256 + tid;

    {
        const uint4* gW = reinterpret_cast<const uint4*>(g_Wh);
        uint4* sW = reinterpret_cast<uint4*>(sWh);
        for (int t = tid; t < 1024; t += 256) sW[t] = gW[t];
    }
    if (tid < 32) {
        reinterpret_cast<__half2*>(dyn + OFF_BC2)[tid] =
            __floats2half2_rn(g_bc[2 * tid], g_bc[2 * tid + 1]);
        reinterpret_cast<__half2*>(dyn + OFF_BF2)[tid] =
            __floats2half2_rn(g_bf1a[2 * tid], g_bf1a[2 * tid + 1]);
        reinterpret_cast<__half2*>(dyn + OFF_FB1H)[tid] =
            __floats2half2_rn(fb1[2 * tid], fb1[2 * tid + 1]);
        reinterpret_cast<__half2*>(dyn + OFF_CW2H)[tid] =
            __floats2half2_rn(cw2[2 * tid], cw2[2 * tid + 1]);
    }
    if (tid < 64) {
        dyn[OFF_A + tid] = g_A[i * 64 + tid];
        dyn[OFF_C + tid] = g_Cw[tid];
    }
    if (tid < 3) dyn[OFF_XI + tid] = x[i * 3 + tid];
    __syncthreads();

    // ---- phase A: geometry + v (fast silu fp32; store fp16, column-private) ----
    float dxr0 = dyn[OFF_XI + 0] - x[j * 3 + 0];
    float dxr1 = dyn[OFF_XI + 1] - x[j * 3 + 1];
    float dxr2 = dyn[OFF_XI + 2] - x[j * 3 + 2];
    float nrm = sqrtf(dxr0 * dxr0 + dxr1 * dxr1 + dxr2 * dxr2 + EPSF);
    float inv1 = __fdividef(1.f, nrm + 1.f);
    float w = g_w[i * NN + j];
    swt[tid] = w;
    float d0 = dxr0 * inv1, d1 = dxr1 * inv1, d2 = dxr2 * inv1;
    dyn[OFF_DIR + 0 * 256 + tid] = d0;
    dyn[OFF_DIR + 1 * 256 + tid] = d1;
    dyn[OFF_DIR + 2 * 256 + tid] = d2;
    sdh[0 * 260 + tid] = __float2half(d0);
    sdh[1 * 260 + tid] = __float2half(d1);
    sdh[2 * 260 + tid] = __float2half(d2);

#pragma unroll 8
    for (int k = 0; k < 64; k++) {
        float b = g_Bt[k * NN + j];
        svh[k * SVH_STR + tid] = __float2half(silu_fast(dyn[OFF_A + k] + b + nrm * dyn[OFF_C + k]));
    }
    __syncthreads();

    // ---- cv = sum_j w*v (fp32, sensitive path) ----
    {
        int k = tid & 63, qq = tid >> 6;
        const __half2* vp = reinterpret_cast<const __half2*>(svh + k * SVH_STR + qq * 64);
        const float* wp = swt + qq * 64;
        float sacc = 0.f;
#pragma unroll 8
        for (int m = 0; m < 32; m++) {
            __half2 p = vp[m];
            sacc += wp[2 * m] * __low2float(p) + wp[2 * m + 1] * __high2float(p);
        }
        dyn[OFF_CVP + k * 4 + qq] = sacc;
    }
    __syncthreads();
    if (tid < 64) {
        const float4 p = *reinterpret_cast<const float4*>(dyn + OFF_CVP + tid * 4);
        atomicAdd(&g_cv[i * 64 + tid], p.x + p.y + p.z + p.w);
    }

    const __half2 hz = __float2half2_rn(0.f);

    // ---- pass 1: Pc = v @ Wc + bc (acc init = bc2) -> phi ----
    {
        const __half2* bc2 = reinterpret_cast<const __half2*>(dyn + OFF_BC2);
        __half2 acc[32];
#pragma unroll
        for (int t = 0; t < 32; t++) acc[t] = bc2[t];
#pragma unroll 4
        for (int kk = 0; kk < 64; kk++) {
            __half2 v2 = __half2half2(svh[kk * SVH_STR + tid]);
            const uint4* wr = reinterpret_cast<const uint4*>(sWh + kk * 128);
#pragma unroll
            for (int c = 0; c < 8; c++) {
                uint4 q = wr[c];
                acc[4 * c + 0] = __hfma2(v2, u2h2(q.x), acc[4 * c + 0]);
                acc[4 * c + 1] = __hfma2(v2, u2h2(q.y), acc[4 * c + 1]);
                acc[4 * c + 2] = __hfma2(v2, u2h2(q.z), acc[4 * c + 2]);
                acc[4 * c + 3] = __hfma2(v2, u2h2(q.w), acc[4 * c + 3]);
            }
        }
        const __half2* cw2h = reinterpret_cast<const __half2*>(dyn + OFF_CW2H);
        __half2 ph2 = hz;
#pragma unroll
        for (int t = 0; t < 32; t++)
            ph2 = __hfma2(silu_h2(acc[t]), cw2h[t], ph2);
        float phi = __low2float(ph2) + __high2float(ph2);
        dyn[OFF_SPHI + tid] = phi * (nrm + 1.f);  // xacc = sum dir * sphi
    }

    // ---- pass 2: Pf = v @ Wf + bf (acc init = bf2) -> S in-place ----
    {
        const __half2* bf2 = reinterpret_cast<const __half2*>(dyn + OFF_BF2);
        __half2 acc[32];
#pragma unroll
        for (int t = 0; t < 32; t++) acc[t] = bf2[t];
#pragma unroll 4
        for (int kk = 0; kk < 64; kk++) {
            __half2 v2 = __half2half2(svh[kk * SVH_STR + tid]);
            const uint4* wr = reinterpret_cast<const uint4*>(sWh + kk * 128 + 64);
#pragma unroll
            for (int c = 0; c < 8; c++) {
                uint4 q = wr[c];
                acc[4 * c + 0] = __hfma2(v2, u2h2(q.x), acc[4 * c + 0]);
                acc[4 * c + 1] = __hfma2(v2, u2h2(q.y), acc[4 * c + 1]);
                acc[4 * c + 2] = __hfma2(v2, u2h2(q.z), acc[4 * c + 2]);
                acc[4 * c + 3] = __hfma2(v2, u2h2(q.w), acc[4 * c + 3]);
            }
        }
        const __half2* fb1h = reinterpret_cast<const __half2*>(dyn + OFF_FB1H);
        __half2 w2 = __float2half2_rn(w);
#pragma unroll
        for (int t = 0; t < 32; t++) {
            __half2 s2 = silu_h2(__hfma2(w2, acc[t], fb1h[t]));
            svh[(2 * t) * SVH_STR + tid] = __low2half(s2);
            svh[(2 * t + 1) * SVH_STR + tid] = __high2half(s2);
        }
    }
    __syncthreads();

    // ---- epilogue: M[k][d] (half2 chunked), xacc, Dsum ----
    if (tid < 192) {
        int k = tid / 3, d = tid - 3 * k;
        const __half2* sp = reinterpret_cast<const __half2*>(svh + k * SVH_STR);
        const __half2* dph = reinterpret_cast<const __half2*>(sdh + d * 260);
        float accf = 0.f;
#pragma unroll
        for (int ch = 0; ch < 4; ch++) {
            __half2 a2 = hz;
#pragma unroll 8
            for (int m = ch * 32; m < ch * 32 + 32; m++) a2 = __hfma2(sp[m], dph[m], a2);
            accf += __low2float(a2) + __high2float(a2);
        }
        atomicAdd(&g_M[i * 192 + k * 3 + d], accf);
    } else if (tid < 195) {
        int d = tid - 192;
        const float* dp = dyn + OFF_DIR + d * 256;
        const float* pp = dyn + OFF_SPHI;
        float sacc = 0.f;
#pragma unroll 8
        for (int jj = 0; jj < 256; jj++) sacc += dp[jj] * pp[jj];
        atomicAdd(&g_xacc[i * 4 + d], sacc);
    } else if (tid < 198) {
        int d = tid - 195;
        const float* dp = dyn + OFF_DIR + d * 256;
        float sacc = 0.f;
#pragma unroll 8
        for (int jj = 0; jj < 256; jj++) sacc += dp[jj];
        atomicAdd(&g_Dsum[i * 4 + d], sacc);
    }
}

// ---------------- K6: node MLPs, 4 nodes/block, 4-way ILP accumulators ------------
__global__ void __launch_bounds__(256, 2) k_final(
        const float* __restrict__ h, const float* __restrict__ x,
        const float* __restrict__ ew2, const float* __restrict__ eb2,
        const float* __restrict__ nw1, const float* __restrict__ nb1,
        const float* __restrict__ nw2, const float* __restrict__ nb2,
        const float* __restrict__ pw1, const float* __restrict__ pb1,
        const float* __restrict__ pw2, const float* __restrict__ pb2,
        const float* __restrict__ fw2, const float* __restrict__ fb2,
        float* __restrict__ out, int write_x) {
    __shared__ float sM[4][192], sq[4][32], p1[4][64], nin[4][192], n1[4][64], scv[4][64];
    int li = threadIdx.x >> 6, t = threadIdx.x & 63;
    int i = blockIdx.x * 4 + li;
    scv[li][t] = g_cv[i * 64 + t];
    for (int tt = t; tt < 192; tt += 64) sM[li][tt] = g_M[i * 192 + tt];
    __syncthreads();
    if (t < 32) {
        int c = t;
        float ds0 = g_Dsum[i * 4 + 0], ds1 = g_Dsum[i * 4 + 1], ds2 = g_Dsum[i * 4 + 2];
        float fb = fb2[c];
        float a0 = fb * ds0, a1 = fb * ds1, a2 = fb * ds2;
#pragma unroll 8
        for (int k = 0; k < 64; k++) {
            float f = fw2[k * 32 + c];
            a0 += f * sM[li][k * 3 + 0];
            a1 += f * sM[li][k * 3 + 1];
            a2 += f * sM[li][k * 3 + 2];
        }
        a0 *= (1.f / 1024.f);
        a1 *= (1.f / 1024.f);
        a2 *= (1.f / 1024.f);
        sq[li][c] = a0 * a0 + a1 * a1 + a2 * a2;
    }
    __syncthreads();
    {
        // h_agg = cv @ ew2 (+ wsum*eb2), 4-way split accumulators
        float a0 = 0.f, a1 = 0.f, a2 = 0.f, a3 = 0.f;
#pragma unroll 4
        for (int m = 0; m < 64; m += 4) {
            a0 += scv[li][m + 0] * ew2[(m + 0) * 64 + t];
            a1 += scv[li][m + 1] * ew2[(m + 1) * 64 + t];
            a2 += scv[li][m + 2] * ew2[(m + 2) * 64 + t];
            a3 += scv[li][m + 3] * ew2[(m + 3) * 64 + t];
        }
        nin[li][64 + t] = g_wsum[i] * eb2[t] + (a0 + a1) + (a2 + a3);
        float b0 = pb1[t], b1 = 0.f, b2 = 0.f, b3 = 0.f;
#pragma unroll 4
        for (int c = 0; c < 32; c += 4) {
            b0 += sq[li][c + 0] * pw1[(c + 0) * 64 + t];
            b1 += sq[li][c + 1] * pw1[(c + 1) * 64 + t];
            b2 += sq[li][c + 2] * pw1[(c + 2) * 64 + t];
            b3 += sq[li][c + 3] * pw1[(c + 3) * 64 + t];
        }
        p1[li][t] = silu_f((b0 + b1) + (b2 + b3));
        nin[li][t] = h[i * 64 + t];
    }
    __syncthreads();
    {
        float a0 = pb2[t], a1 = 0.f, a2 = 0.f, a3 = 0.f;
#pragma unroll 4
        for (int m = 0; m < 64; m += 4) {
            a0 += p1[li][m + 0] * pw2[(m + 0) * 64 + t];
            a1 += p1[li][m + 1] * pw2[(m + 1) * 64 + t];
            a2 += p1[li][m + 2] * pw2[(m + 2) * 64 + t];
            a3 += p1[li][m + 3] * pw2[(m + 3) * 64 + t];
        }
        nin[li][128 + t] = (a0 + a1) + (a2 + a3);
    }
    __syncthreads();
    {
        float a0 = nb1[t], a1 = 0.f, a2 = 0.f, a3 = 0.f;
#pragma unroll 4
        for (int m = 0; m < 192; m += 4) {
            a0 += nin[li][m + 0] * nw1[(m + 0) * 64 + t];
            a1 += nin[li][m + 1] * nw1[(m + 1) * 64 + t];
            a2 += nin[li][m + 2] * nw1[(m + 2) * 64 + t];
            a3 += nin[li][m + 3] * nw1[(m + 3) * 64 + t];
        }
        n1[li][t] = silu_f((a0 + a1) + (a2 + a3));
    }
    __syncthreads();
    {
        float a0 = nb2[t], a1 = 0.f, a2 = 0.f, a3 = 0.f;
#pragma unroll 4
        for (int m = 0; m < 64; m += 4) {
            a0 += n1[li][m + 0] * nw2[(m + 0) * 64 + t];
            a1 += n1[li][m + 1] * nw2[(m + 1) * 64 + t];
            a2 += n1[li][m + 2] * nw2[(m + 2) * 64 + t];
            a3 += n1[li][m + 3] * nw2[(m + 3) * 64 + t];
        }
        out[i * 64 + t] = h[i * 64 + t] + (a0 + a1) + (a2 + a3);
    }
    if (write_x && t < 3)
        out[NN * 64 + i * 3 + t] = x[i * 3 + t] + g_xacc[i * 4 + t] * (1.f / 1024.f);
}

// ---------------- host -------------------------------------------------------------
extern "C" void kernel_launch(void* const* d_in, const int* in_sizes, int n_in,
                              void* d_out, int out_size) {
    const float* h = (const float*)d_in[0];
    const float* x = (const float*)d_in[1];
    const float* ew1 = (const float*)d_in[2];
    const float* eb1 = (const float*)d_in[3];
    const float* ew2 = (const float*)d_in[4];
    const float* eb2 = (const float*)d_in[5];
    const float* nw1 = (const float*)d_in[6];
    const float* nb1 = (const float*)d_in[7];
    const float* nw2 = (const float*)d_in[8];
    const float* nb2 = (const float*)d_in[9];
    const float* cw1 = (const float*)d_in[10];
    const float* cb1 = (const float*)d_in[11];
    const float* cw2 = (const float*)d_in[12];
    const float* aw = (const float*)d_in[13];
    const float* ab = (const float*)d_in[14];
    const float* fw1 = (const float*)d_in[15];
    const float* fb1 = (const float*)d_in[16];
    const float* fw2 = (const float*)d_in[17];
    const float* fb2 = (const float*)d_in[18];
    const float* pw1 = (const float*)d_in[19];
    const float* pb1 = (const float*)d_in[20];
    const float* pw2 = (const float*)d_in[21];
    const float* pb2 = (const float*)d_in[22];
    const float* lg = (const float*)d_in[23];
    float* out = (float*)d_out;

    const int K4_SMEM = K4_FLOATS * sizeof(float);  // 58160 B
    cudaFuncSetAttribute(k_pair, cudaFuncAttributeMaxDynamicSharedMemorySize, K4_SMEM);

    int write_x = (out_size >= NN * 64 + NN * 3) ? 1 : 0;

    k_prep<<<PREP_GRID, 64>>>(h, ew1, eb1, ew2, eb2, cw1, cb1, fw1, aw, ab);
    k_edge_attn<<<NN, 256>>>(x, lg);
    k_pair<<<dim3(NN / 256, NN), 256, K4_SMEM>>>(x, fb1, cw2);
    k_final<<<NN / 4, 256>>>(h, x, ew2, eb2, nw1, nb1, nw2, nb2, pw1, pb1, pw2, pb2,
                             fw2, fb2, out, write_x);
}